// round 3
// baseline (speedup 1.0000x reference)
#include <cuda_runtime.h>

// Problem constants: x (1,64,256,256), W (192,64), bias (192), 8x8 windows of 32x32.
#define NWIN 64
#define TOK  1024
#define C    64
#define WELEMS (TOK*C)          // 65536 floats per window per tensor

// Scratch (device globals — no allocation allowed)
__device__ float g_q [NWIN*WELEMS];
__device__ float g_k [NWIN*WELEMS];
__device__ float g_v [NWIN*WELEMS];
__device__ float g_qm[NWIN*WELEMS];
__device__ float g_km[NWIN*WELEMS];
__device__ float g_qr[NWIN*C];
__device__ float g_kr[NWIN*C];
__device__ float g_ar[NWIN*NWIN];

// ---------------------------------------------------------------------------
// Kernel 1: qkv = gather(x) @ W^T + bias   (M=65536, N=192 in 3 chunks, K=64)
// grid (512, 3): x = token-tile (window*8 + seg of 128 tokens), y = q/k/v chunk
// dyn smem: Xs[64][132] (ch-major, transposed) + Wt[64][64] (ch-major)
// ---------------------------------------------------------------------------
#define QKV_SMEM ((64*132 + 64*64)*4)

__global__ __launch_bounds__(256) void qkv_kernel(const float* __restrict__ x,
                                                  const float* __restrict__ W,
                                                  const float* __restrict__ bias)
{
    extern __shared__ float sm[];
    float* Xs = sm;             // [64][132]
    float* Wt = sm + 64*132;    // [64][64]

    const int tt  = blockIdx.x;
    const int jc  = blockIdx.y;           // 0=q 1=k 2=v
    const int w   = tt >> 3, seg = tt & 7;
    const int wy  = w >> 3,  wx  = w & 7;
    const int t0  = seg * 128;
    const int tid = threadIdx.x;

    // Xs[ch][tl] = x[ch, wy*32 + (t>>5), wx*32 + (t&31)]   (coalesced gmem reads)
    #pragma unroll
    for (int i = 0; i < 32; i++) {
        int idx = tid + i*256;            // 8192 elems
        int ch = idx >> 7, tl = idx & 127;
        int t  = t0 + tl;
        Xs[ch*132 + tl] = x[ch*65536 + (wy*32 + (t>>5))*256 + wx*32 + (t&31)];
    }
    // Wt[ch][jl] = W[(jc*64+jl)*64 + ch]  (L2-resident, conflict-free smem writes)
    #pragma unroll
    for (int i = 0; i < 16; i++) {
        int idx = tid + i*256;            // 4096 elems
        int jl = idx & 63, ch = idx >> 6;
        Wt[ch*64 + jl] = W[(jc*64 + jl)*64 + ch];
    }
    __syncthreads();

    const int ty = tid >> 4, tx = tid & 15;
    const int r0 = ty*8, c0 = tx*4;
    float4 b4 = *(const float4*)&bias[jc*64 + c0];
    float4 acc[8];
    #pragma unroll
    for (int r = 0; r < 8; r++) acc[r] = b4;

    #pragma unroll 8
    for (int kk = 0; kk < 64; kk++) {
        float4 a0 = *(float4*)&Xs[kk*132 + r0];
        float4 a1 = *(float4*)&Xs[kk*132 + r0 + 4];
        float4 b  = *(float4*)&Wt[kk*64  + c0];
        float a[8] = {a0.x,a0.y,a0.z,a0.w,a1.x,a1.y,a1.z,a1.w};
        #pragma unroll
        for (int r = 0; r < 8; r++) {
            acc[r].x += a[r]*b.x; acc[r].y += a[r]*b.y;
            acc[r].z += a[r]*b.z; acc[r].w += a[r]*b.w;
        }
    }

    float* dst = (jc == 0) ? g_q : (jc == 1) ? g_k : g_v;
    #pragma unroll
    for (int r = 0; r < 8; r++)
        *(float4*)&dst[w*WELEMS + (t0 + r0 + r)*64 + c0] = acc[r];
}

// ---------------------------------------------------------------------------
// Kernel 2: q_r / k_r = mean over tokens.  grid (64, 2), 256 thr.
// ---------------------------------------------------------------------------
__global__ void mean_kernel()
{
    __shared__ float red[256];
    const int w   = blockIdx.x;
    const float* src = blockIdx.y ? g_k : g_q;
    float*       dst = blockIdx.y ? g_kr : g_qr;
    const int tid = threadIdx.x;
    const int ch = tid & 63, g = tid >> 6;
    float acc = 0.f;
    for (int t = g*256; t < g*256 + 256; t++)
        acc += src[w*WELEMS + t*64 + ch];
    red[tid] = acc;
    __syncthreads();
    if (tid < 64)
        dst[w*64 + tid] = (red[tid] + red[tid+64] + red[tid+128] + red[tid+192]) * (1.f/1024.f);
}

// ---------------------------------------------------------------------------
// Kernel 3: a_r = relu(q_r @ k_r^T)   (64x64x64 — trivial)
// ---------------------------------------------------------------------------
__global__ void ar_kernel()
{
    __shared__ float qs[NWIN*C], ks[NWIN*C];
    const int tid = threadIdx.x;
    for (int i = tid; i < NWIN*C; i += 256) { qs[i] = g_qr[i]; ks[i] = g_kr[i]; }
    __syncthreads();
    for (int e = tid; e < NWIN*NWIN; e += 256) {
        int i = e >> 6, j = e & 63;
        float s = 0.f;
        #pragma unroll
        for (int c = 0; c < 64; c++) s += qs[i*64 + c] * ks[j*64 + c];
        g_ar[e] = fmaxf(s, 0.f);
    }
}

// ---------------------------------------------------------------------------
// Kernel 4: q_m/k_m[i,pos] = sum_j a_r[i,j] * src[j,pos]
// grid (256, 2), 256 thr; each thread owns one (t,ch) position across windows.
// a_r held transposed in smem so the i-dim vectorizes to float4 broadcasts.
// ---------------------------------------------------------------------------
__global__ __launch_bounds__(256) void mix_kernel()
{
    __shared__ float arsT[NWIN*NWIN];     // [j][i]
    const int tid = threadIdx.x;
    const float* src = blockIdx.y ? g_k  : g_q;
    float*       dst = blockIdx.y ? g_km : g_qm;

    #pragma unroll
    for (int e0 = 0; e0 < 16; e0++) {
        int e = tid + e0*256;
        int i = e & 63, j = e >> 6;
        arsT[j*64 + i] = g_ar[i*64 + j];   // smem writes conflict-free
    }
    __syncthreads();

    const int pos = blockIdx.x*256 + tid;
    float kv[64];
    #pragma unroll
    for (int j = 0; j < 64; j++) kv[j] = src[j*WELEMS + pos];

    #pragma unroll 1
    for (int i0 = 0; i0 < 64; i0 += 8) {
        float4 acc0 = make_float4(0,0,0,0), acc1 = make_float4(0,0,0,0);
        #pragma unroll
        for (int j = 0; j < 64; j++) {
            float kj = kv[j];
            float4 a0 = *(float4*)&arsT[j*64 + i0];
            float4 a1 = *(float4*)&arsT[j*64 + i0 + 4];
            acc0.x += a0.x*kj; acc0.y += a0.y*kj; acc0.z += a0.z*kj; acc0.w += a0.w*kj;
            acc1.x += a1.x*kj; acc1.y += a1.y*kj; acc1.z += a1.z*kj; acc1.w += a1.w*kj;
        }
        dst[(i0+0)*WELEMS + pos] = acc0.x; dst[(i0+1)*WELEMS + pos] = acc0.y;
        dst[(i0+2)*WELEMS + pos] = acc0.z; dst[(i0+3)*WELEMS + pos] = acc0.w;
        dst[(i0+4)*WELEMS + pos] = acc1.x; dst[(i0+5)*WELEMS + pos] = acc1.y;
        dst[(i0+6)*WELEMS + pos] = acc1.z; dst[(i0+7)*WELEMS + pos] = acc1.w;
    }
}

// ---------------------------------------------------------------------------
// Kernel 5 (dominant): per-window  O = relu(Qm @ Km^T) @ V, fused & tiled.
// grid 512 = 64 windows x 8 q-tiles of 128 rows. 256 thr, 2 blocks/SM.
// Stream K/V in 64-row chunks; S staged through smem [t][s] with float4 I/O.
// ---------------------------------------------------------------------------
#define ATTN_SMEM ((64*132 + 64*68 + 64*68 + 128*68)*4)   // 103424 B

__global__ __launch_bounds__(256, 2) void attn_kernel(float* __restrict__ out)
{
    extern __shared__ float sm[];
    float* Qs = sm;                  // [64][132]  (ch-major)
    float* Ks = Qs + 64*132;         // [64][68]   (ch-major)
    float* Vs = Ks + 64*68;          // [64][68]   (s-major, natural)
    float* Ss = Vs + 64*68;          // [128][68]  (t-major)

    const int bx  = blockIdx.x;
    const int w   = bx >> 3, seg = bx & 7;
    const int wy  = w >> 3,  wx  = w & 7;
    const int t0  = seg * 128;
    const int tid = threadIdx.x;
    const int ty  = tid >> 4, tx = tid & 15;
    const int r0  = ty*8, c0 = tx*4;

    // Qs[ch][tl] = q_m[w, t0+tl, ch]
    #pragma unroll
    for (int i = 0; i < 32; i++) {
        int idx = tid + i*256;
        int ch = idx & 63, tl = idx >> 6;
        Qs[ch*132 + tl] = g_qm[w*WELEMS + (t0 + tl)*64 + ch];
    }

    float4 acc_o[8];
    #pragma unroll
    for (int r = 0; r < 8; r++) acc_o[r] = make_float4(0,0,0,0);

    #pragma unroll 1
    for (int chunk = 0; chunk < 16; chunk++) {
        const int s0 = chunk * 64;
        __syncthreads();   // prev-iter readers of Ks/Vs/Ss done; also fences Qs load

        // Ks[ch][sl] = k_m[w, s0+sl, ch]
        #pragma unroll
        for (int i = 0; i < 16; i++) {
            int idx = tid + i*256;
            int ch = idx & 63, sl = idx >> 6;
            Ks[ch*68 + sl] = g_km[w*WELEMS + (s0 + sl)*64 + ch];
        }
        // Vs[sl][ch] = v[w, s0+sl, ch]  (float4)
        #pragma unroll
        for (int i = 0; i < 4; i++) {
            int fidx = tid + i*256;
            int sl = fidx >> 4, c4 = (fidx & 15)*4;
            *(float4*)&Vs[sl*68 + c4] = *(const float4*)&g_v[w*WELEMS + (s0 + sl)*64 + c4];
        }
        __syncthreads();

        // S tile (128x64): rows r0..r0+7, cols c0..c0+3
        float4 accs[8];
        #pragma unroll
        for (int r = 0; r < 8; r++) accs[r] = make_float4(0,0,0,0);
        #pragma unroll 8
        for (int kk = 0; kk < 64; kk++) {
            float4 a0 = *(float4*)&Qs[kk*132 + r0];
            float4 a1 = *(float4*)&Qs[kk*132 + r0 + 4];
            float4 b  = *(float4*)&Ks[kk*68  + c0];
            float a[8] = {a0.x,a0.y,a0.z,a0.w,a1.x,a1.y,a1.z,a1.w};
            #pragma unroll
            for (int r = 0; r < 8; r++) {
                accs[r].x += a[r]*b.x; accs[r].y += a[r]*b.y;
                accs[r].z += a[r]*b.z; accs[r].w += a[r]*b.w;
            }
        }
        // relu -> Ss[t][s] (float4, conflict-free)
        #pragma unroll
        for (int r = 0; r < 8; r++) {
            float4 v = accs[r];
            v.x = fmaxf(v.x, 0.f); v.y = fmaxf(v.y, 0.f);
            v.z = fmaxf(v.z, 0.f); v.w = fmaxf(v.w, 0.f);
            *(float4*)&Ss[(r0 + r)*68 + c0] = v;
        }
        __syncthreads();

        // O (128x64) += S @ V : rows r0..r0+7, channel cols c0..c0+3
        #pragma unroll 2
        for (int sb = 0; sb < 64; sb += 4) {
            float4 vf0 = *(float4*)&Vs[(sb+0)*68 + c0];
            float4 vf1 = *(float4*)&Vs[(sb+1)*68 + c0];
            float4 vf2 = *(float4*)&Vs[(sb+2)*68 + c0];
            float4 vf3 = *(float4*)&Vs[(sb+3)*68 + c0];
            #pragma unroll
            for (int r = 0; r < 8; r++) {
                float4 sf = *(float4*)&Ss[(r0 + r)*68 + sb];   // broadcast across tx
                acc_o[r].x += sf.x*vf0.x + sf.y*vf1.x + sf.z*vf2.x + sf.w*vf3.x;
                acc_o[r].y += sf.x*vf0.y + sf.y*vf1.y + sf.z*vf2.y + sf.w*vf3.y;
                acc_o[r].z += sf.x*vf0.z + sf.y*vf1.z + sf.z*vf2.z + sf.w*vf3.z;
                acc_o[r].w += sf.x*vf0.w + sf.y*vf1.w + sf.z*vf2.w + sf.w*vf3.w;
            }
        }
    }

    __syncthreads();
    // stage O in smem as [t][ch], then write out coalesced in NCHW window layout
    #pragma unroll
    for (int r = 0; r < 8; r++)
        *(float4*)&Ss[(r0 + r)*68 + c0] = acc_o[r];
    __syncthreads();

    #pragma unroll
    for (int i = 0; i < 32; i++) {
        int idx = tid + i*256;
        int ch = idx >> 7, tl = idx & 127;
        int t  = t0 + tl;
        out[ch*65536 + (wy*32 + (t>>5))*256 + wx*32 + (t&31)] = Ss[tl*68 + ch];
    }
}

// ---------------------------------------------------------------------------
extern "C" void kernel_launch(void* const* d_in, const int* in_sizes, int n_in,
                              void* d_out, int out_size)
{
    const float* x    = (const float*)d_in[0];
    const float* W    = (const float*)d_in[1];
    const float* bias = (const float*)d_in[2];
    float* out = (float*)d_out;

    cudaFuncSetAttribute(qkv_kernel,  cudaFuncAttributeMaxDynamicSharedMemorySize, QKV_SMEM);
    cudaFuncSetAttribute(attn_kernel, cudaFuncAttributeMaxDynamicSharedMemorySize, ATTN_SMEM);

    qkv_kernel <<<dim3(512, 3), 256, QKV_SMEM>>>(x, W, bias);
    mean_kernel<<<dim3(64, 2),  256>>>();
    ar_kernel  <<<1,            256>>>();
    mix_kernel <<<dim3(256, 2), 256>>>();
    attn_kernel<<<512,          256, ATTN_SMEM>>>(out);
}

// round 4
// speedup vs baseline: 1.8877x; 1.8877x over previous
#include <cuda_runtime.h>
#include <cstdint>

// Problem constants: x (1,64,256,256), W (192,64), bias (192), 8x8 windows of 32x32.
#define NWIN 64
#define TOK  1024
#define C    64
#define WELEMS (TOK*C)          // 65536 floats per window per tensor

// Scratch (device globals — no allocation allowed)
__device__ float g_q [NWIN*WELEMS];
__device__ float g_k [NWIN*WELEMS];
__device__ float g_v [NWIN*WELEMS];
__device__ float g_qm[NWIN*WELEMS];
__device__ float g_km[NWIN*WELEMS];
__device__ float g_qr[NWIN*C];
__device__ float g_kr[NWIN*C];
__device__ float g_ar[NWIN*NWIN];

// ---------------------------------------------------------------------------
// tf32 helpers
// ---------------------------------------------------------------------------
__device__ __forceinline__ uint32_t f2tf32(float f) {
    uint32_t r;
    asm("cvt.rna.tf32.f32 %0, %1;" : "=r"(r) : "f"(f));
    return r;
}

#define MMA_TF32(d, a, b)                                                     \
    asm volatile(                                                             \
        "mma.sync.aligned.m16n8k8.row.col.f32.tf32.tf32.f32 "                 \
        "{%0,%1,%2,%3}, {%4,%5,%6,%7}, {%8,%9}, {%0,%1,%2,%3};"               \
        : "+f"((d)[0]), "+f"((d)[1]), "+f"((d)[2]), "+f"((d)[3])              \
        : "r"((a)[0]), "r"((a)[1]), "r"((a)[2]), "r"((a)[3]),                 \
          "r"((b)[0]), "r"((b)[1]))

// ---------------------------------------------------------------------------
// Kernel 1: qkv = gather(x) @ W^T + bias   (M=65536, N=192 in 3 chunks, K=64)
// ---------------------------------------------------------------------------
#define QKV_SMEM ((64*132 + 64*64)*4)

__global__ __launch_bounds__(256) void qkv_kernel(const float* __restrict__ x,
                                                  const float* __restrict__ W,
                                                  const float* __restrict__ bias)
{
    extern __shared__ float sm[];
    float* Xs = sm;             // [64][132]
    float* Wt = sm + 64*132;    // [64][64]

    const int tt  = blockIdx.x;
    const int jc  = blockIdx.y;           // 0=q 1=k 2=v
    const int w   = tt >> 3, seg = tt & 7;
    const int wy  = w >> 3,  wx  = w & 7;
    const int t0  = seg * 128;
    const int tid = threadIdx.x;

    #pragma unroll
    for (int i = 0; i < 32; i++) {
        int idx = tid + i*256;
        int ch = idx >> 7, tl = idx & 127;
        int t  = t0 + tl;
        Xs[ch*132 + tl] = x[ch*65536 + (wy*32 + (t>>5))*256 + wx*32 + (t&31)];
    }
    #pragma unroll
    for (int i = 0; i < 16; i++) {
        int idx = tid + i*256;
        int jl = idx & 63, ch = idx >> 6;
        Wt[ch*64 + jl] = W[(jc*64 + jl)*64 + ch];
    }
    __syncthreads();

    const int ty = tid >> 4, tx = tid & 15;
    const int r0 = ty*8, c0 = tx*4;
    float4 b4 = *(const float4*)&bias[jc*64 + c0];
    float4 acc[8];
    #pragma unroll
    for (int r = 0; r < 8; r++) acc[r] = b4;

    #pragma unroll 8
    for (int kk = 0; kk < 64; kk++) {
        float4 a0 = *(float4*)&Xs[kk*132 + r0];
        float4 a1 = *(float4*)&Xs[kk*132 + r0 + 4];
        float4 b  = *(float4*)&Wt[kk*64  + c0];
        float a[8] = {a0.x,a0.y,a0.z,a0.w,a1.x,a1.y,a1.z,a1.w};
        #pragma unroll
        for (int r = 0; r < 8; r++) {
            acc[r].x += a[r]*b.x; acc[r].y += a[r]*b.y;
            acc[r].z += a[r]*b.z; acc[r].w += a[r]*b.w;
        }
    }

    float* dst = (jc == 0) ? g_q : (jc == 1) ? g_k : g_v;
    #pragma unroll
    for (int r = 0; r < 8; r++)
        *(float4*)&dst[w*WELEMS + (t0 + r0 + r)*64 + c0] = acc[r];
}

// ---------------------------------------------------------------------------
// Kernel 2: q_r / k_r = mean over tokens.  grid (64, 2), 256 thr.
// ---------------------------------------------------------------------------
__global__ void mean_kernel()
{
    __shared__ float red[256];
    const int w   = blockIdx.x;
    const float* src = blockIdx.y ? g_k : g_q;
    float*       dst = blockIdx.y ? g_kr : g_qr;
    const int tid = threadIdx.x;
    const int ch = tid & 63, g = tid >> 6;
    float acc = 0.f;
    for (int t = g*256; t < g*256 + 256; t++)
        acc += src[w*WELEMS + t*64 + ch];
    red[tid] = acc;
    __syncthreads();
    if (tid < 64)
        dst[w*64 + tid] = (red[tid] + red[tid+64] + red[tid+128] + red[tid+192]) * (1.f/1024.f);
}

// ---------------------------------------------------------------------------
// Kernel 3: a_r = relu(q_r @ k_r^T)   (64x64x64 — trivial)
// ---------------------------------------------------------------------------
__global__ void ar_kernel()
{
    __shared__ float qs[NWIN*C], ks[NWIN*C];
    const int tid = threadIdx.x;
    for (int i = tid; i < NWIN*C; i += 256) { qs[i] = g_qr[i]; ks[i] = g_kr[i]; }
    __syncthreads();
    for (int e = tid; e < NWIN*NWIN; e += 256) {
        int i = e >> 6, j = e & 63;
        float s = 0.f;
        #pragma unroll
        for (int c = 0; c < 64; c++) s += qs[i*64 + c] * ks[j*64 + c];
        g_ar[e] = fmaxf(s, 0.f);
    }
}

// ---------------------------------------------------------------------------
// Kernel 4: q_m/k_m[i,pos] = sum_j a_r[i,j] * src[j,pos]
// ---------------------------------------------------------------------------
__global__ __launch_bounds__(256) void mix_kernel()
{
    __shared__ float arsT[NWIN*NWIN];     // [j][i]
    const int tid = threadIdx.x;
    const float* src = blockIdx.y ? g_k  : g_q;
    float*       dst = blockIdx.y ? g_km : g_qm;

    #pragma unroll
    for (int e0 = 0; e0 < 16; e0++) {
        int e = tid + e0*256;
        int i = e & 63, j = e >> 6;
        arsT[j*64 + i] = g_ar[i*64 + j];
    }
    __syncthreads();

    const int pos = blockIdx.x*256 + tid;
    float kv[64];
    #pragma unroll
    for (int j = 0; j < 64; j++) kv[j] = src[j*WELEMS + pos];

    #pragma unroll 1
    for (int i0 = 0; i0 < 64; i0 += 8) {
        float4 acc0 = make_float4(0,0,0,0), acc1 = make_float4(0,0,0,0);
        #pragma unroll
        for (int j = 0; j < 64; j++) {
            float kj = kv[j];
            float4 a0 = *(float4*)&arsT[j*64 + i0];
            float4 a1 = *(float4*)&arsT[j*64 + i0 + 4];
            acc0.x += a0.x*kj; acc0.y += a0.y*kj; acc0.z += a0.z*kj; acc0.w += a0.w*kj;
            acc1.x += a1.x*kj; acc1.y += a1.y*kj; acc1.z += a1.z*kj; acc1.w += a1.w*kj;
        }
        dst[(i0+0)*WELEMS + pos] = acc0.x; dst[(i0+1)*WELEMS + pos] = acc0.y;
        dst[(i0+2)*WELEMS + pos] = acc0.z; dst[(i0+3)*WELEMS + pos] = acc0.w;
        dst[(i0+4)*WELEMS + pos] = acc1.x; dst[(i0+5)*WELEMS + pos] = acc1.y;
        dst[(i0+6)*WELEMS + pos] = acc1.z; dst[(i0+7)*WELEMS + pos] = acc1.w;
    }
}

// ---------------------------------------------------------------------------
// Kernel 5 (dominant): per-window  O = relu(Qm @ Km^T) @ V via tf32 mma.sync.
// grid 512 = 64 windows x 8 q-tiles of 128 rows. 256 thr (8 warps), 1 CTA/SM.
// s streamed in 128-row chunks; S (128x128) in fragments -> relu -> smem (tf32)
// -> O += S @ V with persistent fragment accumulators.
//
// SMEM (floats): Qs[128][68] Ks[128][68] Vs[128][68] Ss[128][132]
// Pads chosen so all fragment LDS patterns are bank-conflict-free.
// ---------------------------------------------------------------------------
#define ATTN_SMEM ((3*128*68 + 128*132)*4)   // 172032 B

__global__ __launch_bounds__(256) void attn_kernel(float* __restrict__ out)
{
    extern __shared__ float sm[];
    float* Qs = sm;                  // [128][68] tf32 bits
    float* Ks = Qs + 128*68;         // [128][68] tf32 bits (s-chunk, [s][c])
    float* Vs = Ks + 128*68;         // [128][68] tf32 bits (s-chunk, [s][c])
    float* Ss = Vs + 128*68;         // [128][132] tf32 bits / f32 staging
    uint32_t* Qsu = (uint32_t*)Qs;
    uint32_t* Ksu = (uint32_t*)Ks;
    uint32_t* Vsu = (uint32_t*)Vs;
    uint32_t* Ssu = (uint32_t*)Ss;

    const int bx  = blockIdx.x;
    const int w   = bx >> 3, seg = bx & 7;
    const int wy  = w >> 3,  wx  = w & 7;
    const int t0  = seg * 128;
    const int tid = threadIdx.x;
    const int warp = tid >> 5, lane = tid & 31;
    const int gid  = lane >> 2, tig = lane & 3;   // groupID, threadID-in-group
    const int mwarp = warp >> 1;                  // 0..3 (32 rows each)
    const int nwarp = warp & 1;                   // 0..1

    // Load Q tile (128 x 64) -> smem as tf32, [t][c]
    #pragma unroll
    for (int i = 0; i < 32; i++) {
        int idx = tid + i*256;
        int ch = idx & 63, tl = idx >> 6;
        Qsu[tl*68 + ch] = f2tf32(g_qm[w*WELEMS + (t0 + tl)*64 + ch]);
    }

    // Persistent O accumulators: rows mwarp*32 (2 m-tiles), cols nwarp*32 (4 n-tiles)
    float oacc[2][4][4];
    #pragma unroll
    for (int mt = 0; mt < 2; mt++)
        #pragma unroll
        for (int nt = 0; nt < 4; nt++)
            #pragma unroll
            for (int e = 0; e < 4; e++) oacc[mt][nt][e] = 0.f;

    #pragma unroll 1
    for (int chunk = 0; chunk < 8; chunk++) {
        const int s0 = chunk * 128;
        __syncthreads();   // prev-iter MMA2 readers of Ks/Vs/Ss done

        // Load K chunk [s][c] and V chunk [s][c] as tf32
        #pragma unroll
        for (int i = 0; i < 32; i++) {
            int idx = tid + i*256;
            int ch = idx & 63, sl = idx >> 6;
            Ksu[sl*68 + ch] = f2tf32(g_km[w*WELEMS + (s0 + sl)*64 + ch]);
            Vsu[sl*68 + ch] = f2tf32(g_v [w*WELEMS + (s0 + sl)*64 + ch]);
        }
        __syncthreads();

        // ---- MMA1: S(128x128) = Q(128x64) @ K^T, warp tile 32x64 ----
        float sacc[2][8][4];
        #pragma unroll
        for (int mt = 0; mt < 2; mt++)
            #pragma unroll
            for (int nt = 0; nt < 8; nt++)
                #pragma unroll
                for (int e = 0; e < 4; e++) sacc[mt][nt][e] = 0.f;

        #pragma unroll
        for (int k0 = 0; k0 < 64; k0 += 8) {
            uint32_t a[2][4];
            #pragma unroll
            for (int mt = 0; mt < 2; mt++) {
                int r = mwarp*32 + mt*16 + gid;
                a[mt][0] = Qsu[ r     *68 + k0 + tig];
                a[mt][1] = Qsu[(r + 8)*68 + k0 + tig];
                a[mt][2] = Qsu[ r     *68 + k0 + 4 + tig];
                a[mt][3] = Qsu[(r + 8)*68 + k0 + 4 + tig];
            }
            #pragma unroll
            for (int nt = 0; nt < 8; nt++) {
                int s = nwarp*64 + nt*8 + gid;
                uint32_t b[2];
                b[0] = Ksu[s*68 + k0 + tig];
                b[1] = Ksu[s*68 + k0 + 4 + tig];
                MMA_TF32(sacc[0][nt], a[0], b);
                MMA_TF32(sacc[1][nt], a[1], b);
            }
        }

        // relu + tf32 -> Ss[t][s]
        #pragma unroll
        for (int mt = 0; mt < 2; mt++) {
            int r = mwarp*32 + mt*16 + gid;
            #pragma unroll
            for (int nt = 0; nt < 8; nt++) {
                int cc = nwarp*64 + nt*8 + 2*tig;
                Ssu[ r     *132 + cc    ] = f2tf32(fmaxf(sacc[mt][nt][0], 0.f));
                Ssu[ r     *132 + cc + 1] = f2tf32(fmaxf(sacc[mt][nt][1], 0.f));
                Ssu[(r + 8)*132 + cc    ] = f2tf32(fmaxf(sacc[mt][nt][2], 0.f));
                Ssu[(r + 8)*132 + cc + 1] = f2tf32(fmaxf(sacc[mt][nt][3], 0.f));
            }
        }
        __syncthreads();

        // ---- MMA2: O(128x64) += S(128x128) @ V(128x64), warp tile 32x32 ----
        #pragma unroll
        for (int k0 = 0; k0 < 128; k0 += 8) {
            uint32_t a[2][4];
            #pragma unroll
            for (int mt = 0; mt < 2; mt++) {
                int r = mwarp*32 + mt*16 + gid;
                a[mt][0] = Ssu[ r     *132 + k0 + tig];
                a[mt][1] = Ssu[(r + 8)*132 + k0 + tig];
                a[mt][2] = Ssu[ r     *132 + k0 + 4 + tig];
                a[mt][3] = Ssu[(r + 8)*132 + k0 + 4 + tig];
            }
            #pragma unroll
            for (int nt = 0; nt < 4; nt++) {
                int c = nwarp*32 + nt*8 + gid;
                uint32_t b[2];
                b[0] = Vsu[(k0     + tig)*68 + c];
                b[1] = Vsu[(k0 + 4 + tig)*68 + c];
                MMA_TF32(oacc[0][nt], a[0], b);
                MMA_TF32(oacc[1][nt], a[1], b);
            }
        }
    }

    __syncthreads();
    // Stage O in smem as [t][c] (fp32), then write out coalesced (NCHW windows)
    #pragma unroll
    for (int mt = 0; mt < 2; mt++) {
        int r = mwarp*32 + mt*16 + gid;
        #pragma unroll
        for (int nt = 0; nt < 4; nt++) {
            int c = nwarp*32 + nt*8 + 2*tig;
            Ss[ r     *132 + c    ] = oacc[mt][nt][0];
            Ss[ r     *132 + c + 1] = oacc[mt][nt][1];
            Ss[(r + 8)*132 + c    ] = oacc[mt][nt][2];
            Ss[(r + 8)*132 + c + 1] = oacc[mt][nt][3];
        }
    }
    __syncthreads();

    #pragma unroll
    for (int i = 0; i < 32; i++) {
        int idx = tid + i*256;
        int ch = idx >> 7, tl = idx & 127;
        int t  = t0 + tl;
        out[ch*65536 + (wy*32 + (t>>5))*256 + wx*32 + (t&31)] = Ss[tl*132 + ch];
    }
}

// ---------------------------------------------------------------------------
extern "C" void kernel_launch(void* const* d_in, const int* in_sizes, int n_in,
                              void* d_out, int out_size)
{
    const float* x    = (const float*)d_in[0];
    const float* W    = (const float*)d_in[1];
    const float* bias = (const float*)d_in[2];
    float* out = (float*)d_out;

    cudaFuncSetAttribute(qkv_kernel,  cudaFuncAttributeMaxDynamicSharedMemorySize, QKV_SMEM);
    cudaFuncSetAttribute(attn_kernel, cudaFuncAttributeMaxDynamicSharedMemorySize, ATTN_SMEM);

    qkv_kernel <<<dim3(512, 3), 256, QKV_SMEM>>>(x, W, bias);
    mean_kernel<<<dim3(64, 2),  256>>>();
    ar_kernel  <<<1,            256>>>();
    mix_kernel <<<dim3(256, 2), 256>>>();
    attn_kernel<<<512,          256, ATTN_SMEM>>>(out);
}

// round 5
// speedup vs baseline: 2.3260x; 1.2322x over previous
#include <cuda_runtime.h>
#include <cstdint>

// Problem constants: x (1,64,256,256), W (192,64), bias (192), 8x8 windows of 32x32.
#define NWIN 64
#define TOK  1024
#define C    64
#define WELEMS (TOK*C)          // 65536 floats per window per tensor

// Scratch (device globals — no allocation allowed)
__device__ float g_q [NWIN*WELEMS];
__device__ float g_k [NWIN*WELEMS];
__device__ float g_v [NWIN*WELEMS];
__device__ float g_qm[NWIN*WELEMS];
__device__ float g_km[NWIN*WELEMS];
__device__ float g_qr[NWIN*C];
__device__ float g_kr[NWIN*C];
__device__ float g_ar[NWIN*NWIN];

// ---------------------------------------------------------------------------
// tf32 helpers
// ---------------------------------------------------------------------------
__device__ __forceinline__ uint32_t f2tf32(float f) {
    uint32_t r;
    asm("cvt.rna.tf32.f32 %0, %1;" : "=r"(r) : "f"(f));
    return r;
}

#define MMA_TF32(d, a, b)                                                     \
    asm volatile(                                                             \
        "mma.sync.aligned.m16n8k8.row.col.f32.tf32.tf32.f32 "                 \
        "{%0,%1,%2,%3}, {%4,%5,%6,%7}, {%8,%9}, {%0,%1,%2,%3};"               \
        : "+f"((d)[0]), "+f"((d)[1]), "+f"((d)[2]), "+f"((d)[3])              \
        : "r"((a)[0]), "r"((a)[1]), "r"((a)[2]), "r"((a)[3]),                 \
          "r"((b)[0]), "r"((b)[1]))

// ---------------------------------------------------------------------------
// Kernel 1: qkv = gather(x) @ W^T + bias via tf32 mma.
// grid 512 token-tiles of 128. Out tile 128x192. 8 warps (4m x 2n),
// warp tile 32 x 96. A = X[t][c] (stride 68), B = W^T[c][j] (stride 200).
// Epilogue: +bias, stage in smem [128][196], coalesced float4 stores.
// ---------------------------------------------------------------------------
#define QKV_XS_STRIDE 68
#define QKV_WT_STRIDE 200
#define QKV_SG_STRIDE 196
#define QKV_SMEM ((128*QKV_SG_STRIDE + 192)*4)   // stage union >= Xs+Wt (21504)

__global__ __launch_bounds__(256) void qkv_kernel(const float* __restrict__ x,
                                                  const float* __restrict__ W,
                                                  const float* __restrict__ bias)
{
    extern __shared__ float sm[];
    uint32_t* Xs = (uint32_t*)sm;                         // [128][68] tf32
    uint32_t* Wt = (uint32_t*)(sm + 128*QKV_XS_STRIDE);   // [64][200] tf32
    float*    Sg = sm;                                    // stage [128][196] (union)
    float*    bs = sm + 128*QKV_SG_STRIDE;                // [192] bias

    const int tt  = blockIdx.x;
    const int w   = tt >> 3, seg = tt & 7;
    const int wy  = w >> 3,  wx  = w & 7;
    const int t0  = seg * 128;
    const int tid = threadIdx.x;
    const int warp = tid >> 5, lane = tid & 31;
    const int gid  = lane >> 2, tig = lane & 3;
    const int mwarp = warp >> 1;          // 0..3 -> 32 rows
    const int nwarp = warp & 1;           // 0..1 -> 96 cols

    // Xs[t][ch] = tf32(x[...])  (coalesced gmem over window columns)
    #pragma unroll
    for (int i = 0; i < 32; i++) {
        int idx = tid + i*256;
        int ch = idx >> 7, tl = idx & 127;
        int t  = t0 + tl;
        Xs[tl*QKV_XS_STRIDE + ch] =
            f2tf32(x[ch*65536 + (wy*32 + (t>>5))*256 + wx*32 + (t&31)]);
    }
    // Wt[ch][j] = tf32(W[j][ch]); bias -> smem
    #pragma unroll
    for (int i = 0; i < 48; i++) {
        int idx = tid + i*256;
        int ch = idx & 63, j = idx >> 6;
        Wt[ch*QKV_WT_STRIDE + j] = f2tf32(W[j*64 + ch]);
    }
    if (tid < 192) bs[tid] = bias[tid];
    __syncthreads();

    float acc[2][12][4];
    #pragma unroll
    for (int mt = 0; mt < 2; mt++)
        #pragma unroll
        for (int nt = 0; nt < 12; nt++)
            #pragma unroll
            for (int e = 0; e < 4; e++) acc[mt][nt][e] = 0.f;

    #pragma unroll
    for (int k0 = 0; k0 < 64; k0 += 8) {
        uint32_t a[2][4];
        #pragma unroll
        for (int mt = 0; mt < 2; mt++) {
            int r = mwarp*32 + mt*16 + gid;
            a[mt][0] = Xs[ r     *QKV_XS_STRIDE + k0 + tig];
            a[mt][1] = Xs[(r + 8)*QKV_XS_STRIDE + k0 + tig];
            a[mt][2] = Xs[ r     *QKV_XS_STRIDE + k0 + 4 + tig];
            a[mt][3] = Xs[(r + 8)*QKV_XS_STRIDE + k0 + 4 + tig];
        }
        #pragma unroll
        for (int nt = 0; nt < 12; nt++) {
            int j = nwarp*96 + nt*8 + gid;
            uint32_t b[2];
            b[0] = Wt[(k0     + tig)*QKV_WT_STRIDE + j];
            b[1] = Wt[(k0 + 4 + tig)*QKV_WT_STRIDE + j];
            MMA_TF32(acc[0][nt], a[0], b);
            MMA_TF32(acc[1][nt], a[1], b);
        }
    }
    __syncthreads();   // done reading Xs/Wt; stage region reuses them

    // stage acc (+bias) -> Sg[t][j]
    #pragma unroll
    for (int mt = 0; mt < 2; mt++) {
        int r = mwarp*32 + mt*16 + gid;
        #pragma unroll
        for (int nt = 0; nt < 12; nt++) {
            int j = nwarp*96 + nt*8 + 2*tig;
            Sg[ r     *QKV_SG_STRIDE + j    ] = acc[mt][nt][0] + bs[j];
            Sg[ r     *QKV_SG_STRIDE + j + 1] = acc[mt][nt][1] + bs[j+1];
            Sg[(r + 8)*QKV_SG_STRIDE + j    ] = acc[mt][nt][2] + bs[j];
            Sg[(r + 8)*QKV_SG_STRIDE + j + 1] = acc[mt][nt][3] + bs[j+1];
        }
    }
    __syncthreads();

    // coalesced float4 copy-out: 128 rows x 48 float4 (16 per tensor)
    #pragma unroll
    for (int p = 0; p < 24; p++) {
        int idx = tid + p*256;
        int t  = idx / 48, f4 = idx % 48;
        float4 v = *(float4*)&Sg[t*QKV_SG_STRIDE + f4*4];
        float* dst = (f4 < 16) ? g_q : (f4 < 32) ? g_k : g_v;
        int jj = (f4 & 15) * 4;
        *(float4*)&dst[w*WELEMS + (t0 + t)*64 + jj] = v;
    }
}

// ---------------------------------------------------------------------------
// Kernel 2: q_r / k_r = mean over tokens.  grid (64, 2), 256 thr.
// ---------------------------------------------------------------------------
__global__ void mean_kernel()
{
    __shared__ float red[256];
    const int w   = blockIdx.x;
    const float* src = blockIdx.y ? g_k : g_q;
    float*       dst = blockIdx.y ? g_kr : g_qr;
    const int tid = threadIdx.x;
    const int ch = tid & 63, g = tid >> 6;
    float acc = 0.f;
    for (int t = g*256; t < g*256 + 256; t++)
        acc += src[w*WELEMS + t*64 + ch];
    red[tid] = acc;
    __syncthreads();
    if (tid < 64)
        dst[w*64 + tid] = (red[tid] + red[tid+64] + red[tid+128] + red[tid+192]) * (1.f/1024.f);
}

// ---------------------------------------------------------------------------
// Kernel 3: a_r = relu(q_r @ k_r^T)   (64x64x64 — trivial)
// ---------------------------------------------------------------------------
__global__ void ar_kernel()
{
    __shared__ float qs[NWIN*C], ks[NWIN*C];
    const int tid = threadIdx.x;
    for (int i = tid; i < NWIN*C; i += 256) { qs[i] = g_qr[i]; ks[i] = g_kr[i]; }
    __syncthreads();
    for (int e = tid; e < NWIN*NWIN; e += 256) {
        int i = e >> 6, j = e & 63;
        float s = 0.f;
        #pragma unroll
        for (int c = 0; c < 64; c++) s += qs[i*64 + c] * ks[j*64 + c];
        g_ar[e] = fmaxf(s, 0.f);
    }
}

// ---------------------------------------------------------------------------
// Kernel 4: q_m/k_m = a_r @ src, as tf32 mma GEMM (M=64, K=64, N=65536).
// grid (256, 2): 256 pos-tiles of 256. Out tile 64x256. 8 warps (4m x 2n),
// warp tile 16 x 128. A = ar[i][j] (stride 68), B = src[j][pos] (stride 264).
// Staged epilogue -> perfect float4 stores.
// ---------------------------------------------------------------------------
#define MIX_AR_STRIDE 68
#define MIX_B_STRIDE  264
#define MIX_SG_STRIDE 260
#define MIX_SMEM ((64*MIX_AR_STRIDE + 64*MIX_B_STRIDE)*4)

__global__ __launch_bounds__(256) void mix_kernel()
{
    extern __shared__ float sm[];
    uint32_t* ars = (uint32_t*)sm;                        // [64][68] tf32
    uint32_t* Bs  = (uint32_t*)(sm + 64*MIX_AR_STRIDE);   // [64][264] tf32
    float*    Sg  = sm + 64*MIX_AR_STRIDE;                // stage [64][260] (union w/ Bs)

    const int tid = threadIdx.x;
    const int warp = tid >> 5, lane = tid & 31;
    const int gid  = lane >> 2, tig = lane & 3;
    const int mwarp = warp >> 1;          // 0..3 -> 16 rows
    const int nwarp = warp & 1;           // 0..1 -> 128 cols
    const float* src = blockIdx.y ? g_k  : g_q;
    float*       dst = blockIdx.y ? g_km : g_qm;
    const int pos0 = blockIdx.x * 256;

    #pragma unroll
    for (int p = 0; p < 16; p++) {
        int e = tid + p*256;
        int i = e >> 6, j = e & 63;
        ars[i*MIX_AR_STRIDE + j] = f2tf32(g_ar[e]);
    }
    // B tile: src[j][pos0..pos0+255], float4 loads
    #pragma unroll
    for (int p = 0; p < 16; p++) {
        int idx = tid + p*256;              // 4096 float4
        int j = idx >> 6, f4 = idx & 63;
        float4 v = *(const float4*)&src[j*WELEMS + pos0 + f4*4];
        uint32_t* d = &Bs[j*MIX_B_STRIDE + f4*4];
        d[0] = f2tf32(v.x); d[1] = f2tf32(v.y); d[2] = f2tf32(v.z); d[3] = f2tf32(v.w);
    }
    __syncthreads();

    float acc[16][4];
    #pragma unroll
    for (int nt = 0; nt < 16; nt++)
        #pragma unroll
        for (int e = 0; e < 4; e++) acc[nt][e] = 0.f;

    #pragma unroll
    for (int k0 = 0; k0 < 64; k0 += 8) {
        uint32_t a[4];
        int r = mwarp*16 + gid;
        a[0] = ars[ r     *MIX_AR_STRIDE + k0 + tig];
        a[1] = ars[(r + 8)*MIX_AR_STRIDE + k0 + tig];
        a[2] = ars[ r     *MIX_AR_STRIDE + k0 + 4 + tig];
        a[3] = ars[(r + 8)*MIX_AR_STRIDE + k0 + 4 + tig];
        #pragma unroll
        for (int nt = 0; nt < 16; nt++) {
            int n = nwarp*128 + nt*8 + gid;
            uint32_t b[2];
            b[0] = Bs[(k0     + tig)*MIX_B_STRIDE + n];
            b[1] = Bs[(k0 + 4 + tig)*MIX_B_STRIDE + n];
            MMA_TF32(acc[nt], a, b);
        }
    }
    __syncthreads();   // done reading Bs; stage region reuses it

    {
        int r = mwarp*16 + gid;
        #pragma unroll
        for (int nt = 0; nt < 16; nt++) {
            int n = nwarp*128 + nt*8 + 2*tig;
            Sg[ r     *MIX_SG_STRIDE + n    ] = acc[nt][0];
            Sg[ r     *MIX_SG_STRIDE + n + 1] = acc[nt][1];
            Sg[(r + 8)*MIX_SG_STRIDE + n    ] = acc[nt][2];
            Sg[(r + 8)*MIX_SG_STRIDE + n + 1] = acc[nt][3];
        }
    }
    __syncthreads();

    // coalesced float4 copy-out: 64 rows x 64 float4
    #pragma unroll
    for (int p = 0; p < 16; p++) {
        int idx = tid + p*256;
        int i = idx >> 6, f4 = idx & 63;
        float4 v = *(float4*)&Sg[i*MIX_SG_STRIDE + f4*4];
        *(float4*)&dst[i*WELEMS + pos0 + f4*4] = v;
    }
}

// ---------------------------------------------------------------------------
// Kernel 5: per-window  O = relu(Qm @ Km^T) @ V via tf32 mma.sync (unchanged).
// ---------------------------------------------------------------------------
#define ATTN_SMEM ((3*128*68 + 128*132)*4)   // 172032 B

__global__ __launch_bounds__(256) void attn_kernel(float* __restrict__ out)
{
    extern __shared__ float sm[];
    float* Qs = sm;                  // [128][68] tf32 bits
    float* Ks = Qs + 128*68;         // [128][68] tf32 bits (s-chunk, [s][c])
    float* Vs = Ks + 128*68;         // [128][68] tf32 bits (s-chunk, [s][c])
    float* Ss = Vs + 128*68;         // [128][132] tf32 bits / f32 staging
    uint32_t* Qsu = (uint32_t*)Qs;
    uint32_t* Ksu = (uint32_t*)Ks;
    uint32_t* Vsu = (uint32_t*)Vs;
    uint32_t* Ssu = (uint32_t*)Ss;

    const int bx  = blockIdx.x;
    const int w   = bx >> 3, seg = bx & 7;
    const int wy  = w >> 3,  wx  = w & 7;
    const int t0  = seg * 128;
    const int tid = threadIdx.x;
    const int warp = tid >> 5, lane = tid & 31;
    const int gid  = lane >> 2, tig = lane & 3;
    const int mwarp = warp >> 1;
    const int nwarp = warp & 1;

    #pragma unroll
    for (int i = 0; i < 32; i++) {
        int idx = tid + i*256;
        int ch = idx & 63, tl = idx >> 6;
        Qsu[tl*68 + ch] = f2tf32(g_qm[w*WELEMS + (t0 + tl)*64 + ch]);
    }

    float oacc[2][4][4];
    #pragma unroll
    for (int mt = 0; mt < 2; mt++)
        #pragma unroll
        for (int nt = 0; nt < 4; nt++)
            #pragma unroll
            for (int e = 0; e < 4; e++) oacc[mt][nt][e] = 0.f;

    #pragma unroll 1
    for (int chunk = 0; chunk < 8; chunk++) {
        const int s0 = chunk * 128;
        __syncthreads();

        #pragma unroll
        for (int i = 0; i < 32; i++) {
            int idx = tid + i*256;
            int ch = idx & 63, sl = idx >> 6;
            Ksu[sl*68 + ch] = f2tf32(g_km[w*WELEMS + (s0 + sl)*64 + ch]);
            Vsu[sl*68 + ch] = f2tf32(g_v [w*WELEMS + (s0 + sl)*64 + ch]);
        }
        __syncthreads();

        float sacc[2][8][4];
        #pragma unroll
        for (int mt = 0; mt < 2; mt++)
            #pragma unroll
            for (int nt = 0; nt < 8; nt++)
                #pragma unroll
                for (int e = 0; e < 4; e++) sacc[mt][nt][e] = 0.f;

        #pragma unroll
        for (int k0 = 0; k0 < 64; k0 += 8) {
            uint32_t a[2][4];
            #pragma unroll
            for (int mt = 0; mt < 2; mt++) {
                int r = mwarp*32 + mt*16 + gid;
                a[mt][0] = Qsu[ r     *68 + k0 + tig];
                a[mt][1] = Qsu[(r + 8)*68 + k0 + tig];
                a[mt][2] = Qsu[ r     *68 + k0 + 4 + tig];
                a[mt][3] = Qsu[(r + 8)*68 + k0 + 4 + tig];
            }
            #pragma unroll
            for (int nt = 0; nt < 8; nt++) {
                int s = nwarp*64 + nt*8 + gid;
                uint32_t b[2];
                b[0] = Ksu[s*68 + k0 + tig];
                b[1] = Ksu[s*68 + k0 + 4 + tig];
                MMA_TF32(sacc[0][nt], a[0], b);
                MMA_TF32(sacc[1][nt], a[1], b);
            }
        }

        #pragma unroll
        for (int mt = 0; mt < 2; mt++) {
            int r = mwarp*32 + mt*16 + gid;
            #pragma unroll
            for (int nt = 0; nt < 8; nt++) {
                int cc = nwarp*64 + nt*8 + 2*tig;
                Ssu[ r     *132 + cc    ] = f2tf32(fmaxf(sacc[mt][nt][0], 0.f));
                Ssu[ r     *132 + cc + 1] = f2tf32(fmaxf(sacc[mt][nt][1], 0.f));
                Ssu[(r + 8)*132 + cc    ] = f2tf32(fmaxf(sacc[mt][nt][2], 0.f));
                Ssu[(r + 8)*132 + cc + 1] = f2tf32(fmaxf(sacc[mt][nt][3], 0.f));
            }
        }
        __syncthreads();

        #pragma unroll
        for (int k0 = 0; k0 < 128; k0 += 8) {
            uint32_t a[2][4];
            #pragma unroll
            for (int mt = 0; mt < 2; mt++) {
                int r = mwarp*32 + mt*16 + gid;
                a[mt][0] = Ssu[ r     *132 + k0 + tig];
                a[mt][1] = Ssu[(r + 8)*132 + k0 + tig];
                a[mt][2] = Ssu[ r     *132 + k0 + 4 + tig];
                a[mt][3] = Ssu[(r + 8)*132 + k0 + 4 + tig];
            }
            #pragma unroll
            for (int nt = 0; nt < 4; nt++) {
                int c = nwarp*32 + nt*8 + gid;
                uint32_t b[2];
                b[0] = Vsu[(k0     + tig)*68 + c];
                b[1] = Vsu[(k0 + 4 + tig)*68 + c];
                MMA_TF32(oacc[0][nt], a[0], b);
                MMA_TF32(oacc[1][nt], a[1], b);
            }
        }
    }

    __syncthreads();
    #pragma unroll
    for (int mt = 0; mt < 2; mt++) {
        int r = mwarp*32 + mt*16 + gid;
        #pragma unroll
        for (int nt = 0; nt < 4; nt++) {
            int c = nwarp*32 + nt*8 + 2*tig;
            Ss[ r     *132 + c    ] = oacc[mt][nt][0];
            Ss[ r     *132 + c + 1] = oacc[mt][nt][1];
            Ss[(r + 8)*132 + c    ] = oacc[mt][nt][2];
            Ss[(r + 8)*132 + c + 1] = oacc[mt][nt][3];
        }
    }
    __syncthreads();

    #pragma unroll
    for (int i = 0; i < 32; i++) {
        int idx = tid + i*256;
        int ch = idx >> 7, tl = idx & 127;
        int t  = t0 + tl;
        out[ch*65536 + (wy*32 + (t>>5))*256 + wx*32 + (t&31)] = Ss[tl*132 + ch];
    }
}

// ---------------------------------------------------------------------------
extern "C" void kernel_launch(void* const* d_in, const int* in_sizes, int n_in,
                              void* d_out, int out_size)
{
    const float* x    = (const float*)d_in[0];
    const float* W    = (const float*)d_in[1];
    const float* bias = (const float*)d_in[2];
    float* out = (float*)d_out;

    cudaFuncSetAttribute(qkv_kernel,  cudaFuncAttributeMaxDynamicSharedMemorySize, QKV_SMEM);
    cudaFuncSetAttribute(mix_kernel,  cudaFuncAttributeMaxDynamicSharedMemorySize, MIX_SMEM);
    cudaFuncSetAttribute(attn_kernel, cudaFuncAttributeMaxDynamicSharedMemorySize, ATTN_SMEM);

    qkv_kernel <<<512,          256, QKV_SMEM>>>(x, W, bias);
    mean_kernel<<<dim3(64, 2),  256>>>();
    ar_kernel  <<<1,            256>>>();
    mix_kernel <<<dim3(256, 2), 256, MIX_SMEM>>>();
    attn_kernel<<<512,          256, ATTN_SMEM>>>(out);
}